// round 2
// baseline (speedup 1.0000x reference)
#include <cuda_runtime.h>
#include <math.h>
#include <stdint.h>

// ---------------- problem constants ----------------
#define BB   64      // batch
#define SS   128     // stoch size
#define DD   1024    // deter size
#define HH   1024    // hidden
#define EE   1024    // encoded obs
#define OO   1152    // S + D
#define T0   36
#define FF   6

// ---------------- scratch (device globals; no allocation allowed) ----------
__device__ float g_P  [16 * 64 * 1024];   // generic split-K partials (4 MB)
__device__ float g_Pgh[ 4 * 64 * 3072];   // gh partials
__device__ float g_Pgi[ 8 * 64 * 3072];   // gi partials
__device__ float g_h  [64 * 1024];
__device__ float g_hq1[64 * 1024];
__device__ float g_hq2[64 * 1024];
__device__ float g_det[2 * 64 * 1024];    // ping-pong GRU state
__device__ float g_out1[64 * 6 * 1152];
__device__ float g_out2[64 * 1 * 1152];

// ---------------- f32x2 packed math (sm_103a FFMA2 trick) ------------------
typedef unsigned long long ull;

__device__ __forceinline__ ull pk2(float lo, float hi) {
    ull r; asm("mov.b64 %0, {%1, %2};" : "=l"(r) : "f"(lo), "f"(hi)); return r;
}
__device__ __forceinline__ void fma2(ull &d, ull a, ull b) {
    asm("fma.rn.f32x2 %0, %1, %2, %0;" : "+l"(d) : "l"(a), "l"(b));
}
__device__ __forceinline__ void upk2(ull v, float &lo, float &hi) {
    asm("mov.b64 {%0, %1}, %2;" : "=f"(lo), "=f"(hi) : "l"(v));
}

__device__ __forceinline__ float eluf(float x)  { return x > 0.f ? x : (expf(x) - 1.f); }
__device__ __forceinline__ float sigm(float x)  { return 1.f / (1.f + expf(-x)); }
__device__ __forceinline__ float softp(float x) { return x > 20.f ? x : log1pf(expf(x)); }

// ---------------- split-K GEMM partials -------------------------------------
// C_partial[s] = A[:, s*Ksz:(s+1)*Ksz] @ W[s*Ksz:(s+1)*Ksz, :]
// A = concat(A1[64,K1], A2[64,K2]) with per-row strides; null ptr => zeros.
// Block tile M64 x N128, 128 threads, thread tile 8x8, M-paired f32x2 accum.
struct GemmDesc {
    const float *A1, *A2, *W;
    float *P;                 // [SK][64][N]
    int lda1, lda2, K1, K2;
    int N;                    // output width == W row stride
    int SK, Ksz;              // Ksz multiple of 16
    int nblk;                 // N / 128
};

__global__ __launch_bounds__(128) void gemm_part2(GemmDesc da, GemmDesc db, int blocksA) {
    GemmDesc d;
    int bx = blockIdx.x;
    if (bx < blocksA) d = da; else { d = db; bx -= blocksA; }
    const int s  = bx / d.nblk;
    const int nb = bx % d.nblk;
    const int n0 = nb * 128;
    const int ks = s * d.Ksz;
    const int kend = ks + d.Ksz;

    __shared__ float As[16 * 64];    // [k][m]
    __shared__ float Ws[16 * 128];   // [k][n]

    const int tid = threadIdx.x;
    const int rb = (tid >> 4) * 8;   // row base (0..56)
    const int cb = (tid & 15) * 8;   // col base (0..120)

    ull acc[4][8];
#pragma unroll
    for (int i = 0; i < 4; ++i)
#pragma unroll
        for (int j = 0; j < 8; ++j) acc[i][j] = 0ull;

    for (int k0 = ks; k0 < kend; k0 += 16) {
        // ---- load A chunk (64 rows x 16 k), store transposed [k][m] ----
#pragma unroll
        for (int i = 0; i < 2; ++i) {
            int u   = tid * 2 + i;       // 0..255 float4 units
            int row = u >> 2;
            int q   = u & 3;
            int kg  = k0 + q * 4;
            float4 v = make_float4(0.f, 0.f, 0.f, 0.f);
            if (kg < d.K1) {
                if (d.A1) v = *(const float4 *)(d.A1 + (size_t)row * d.lda1 + kg);
            } else {
                if (d.A2) v = *(const float4 *)(d.A2 + (size_t)row * d.lda2 + (kg - d.K1));
            }
            As[(q * 4 + 0) * 64 + row] = v.x;
            As[(q * 4 + 1) * 64 + row] = v.y;
            As[(q * 4 + 2) * 64 + row] = v.z;
            As[(q * 4 + 3) * 64 + row] = v.w;
        }
        // ---- load W chunk (16 k x 128 n) ----
#pragma unroll
        for (int i = 0; i < 4; ++i) {
            int u   = tid + 128 * i;     // 0..511 float4 units
            int row = u >> 5;
            int q   = u & 31;
            float4 v = *(const float4 *)(d.W + (size_t)(k0 + row) * d.N + n0 + q * 4);
            *(float4 *)&Ws[row * 128 + q * 4] = v;
        }
        __syncthreads();

#pragma unroll
        for (int kk = 0; kk < 16; ++kk) {
            const float *asr = &As[kk * 64 + rb];
            ulonglong2 av  = *(const ulonglong2 *)asr;        // rows rb..rb+3 (2 pairs)
            ulonglong2 av2 = *(const ulonglong2 *)(asr + 4);  // rows rb+4..rb+7
            ull ap[4] = {av.x, av.y, av2.x, av2.y};
            float4 w0 = *(const float4 *)&Ws[kk * 128 + cb];
            float4 w1 = *(const float4 *)&Ws[kk * 128 + cb + 4];
            ull wd[8] = {pk2(w0.x, w0.x), pk2(w0.y, w0.y), pk2(w0.z, w0.z), pk2(w0.w, w0.w),
                         pk2(w1.x, w1.x), pk2(w1.y, w1.y), pk2(w1.z, w1.z), pk2(w1.w, w1.w)};
#pragma unroll
            for (int rp = 0; rp < 4; ++rp)
#pragma unroll
                for (int c = 0; c < 8; ++c) fma2(acc[rp][c], ap[rp], wd[c]);
        }
        __syncthreads();
    }

    // ---- write partial tile ----
    float *Pp = d.P + (size_t)s * 64 * d.N + n0;
#pragma unroll
    for (int rp = 0; rp < 4; ++rp) {
        int r = rb + rp * 2;
        float lo[8], hi[8];
#pragma unroll
        for (int c = 0; c < 8; ++c) upk2(acc[rp][c], lo[c], hi[c]);
        *(float4 *)&Pp[(size_t)r * d.N + cb]           = make_float4(lo[0], lo[1], lo[2], lo[3]);
        *(float4 *)&Pp[(size_t)r * d.N + cb + 4]       = make_float4(lo[4], lo[5], lo[6], lo[7]);
        *(float4 *)&Pp[(size_t)(r + 1) * d.N + cb]     = make_float4(hi[0], hi[1], hi[2], hi[3]);
        *(float4 *)&Pp[(size_t)(r + 1) * d.N + cb + 4] = make_float4(hi[4], hi[5], hi[6], hi[7]);
    }
}

// ---------------- reduce partials + bias + optional ELU ---------------------
__global__ void reduce_act(const float *__restrict__ P, int SK, int N,
                           const float *__restrict__ bias, float *__restrict__ C, int doElu) {
    int idx = blockIdx.x * blockDim.x + threadIdx.x;
    int total = (64 * N) >> 2;
    if (idx >= total) return;
    const float4 *P4 = (const float4 *)P;
    float4 a = P4[idx];
    for (int s = 1; s < SK; ++s) {
        float4 p = P4[idx + (size_t)s * total];
        a.x += p.x; a.y += p.y; a.z += p.z; a.w += p.w;
    }
    float4 b = ((const float4 *)bias)[idx % (N >> 2)];
    a.x += b.x; a.y += b.y; a.z += b.z; a.w += b.w;
    if (doElu) { a.x = eluf(a.x); a.y = eluf(a.y); a.z = eluf(a.z); a.w = eluf(a.w); }
    ((float4 *)C)[idx] = a;
}

// ---------------- fused GRU: reduce gi/gh partials + gates + state ----------
__global__ void gru_fuse(const float *__restrict__ Pgi, int SKi,
                         const float *__restrict__ Pgh, int SKh,
                         const float *__restrict__ bi, const float *__restrict__ bh,
                         const float *__restrict__ det, float *__restrict__ detn,
                         float *__restrict__ outc, int ldo) {
    int idx = blockIdx.x * blockDim.x + threadIdx.x;   // per float4 of [64][1024]
    if (idx >= 64 * 1024 / 4) return;
    int b = idx >> 8;
    int j = (idx & 255) << 2;

    float4 gir = make_float4(0,0,0,0), giz = gir, gin = gir;
    float4 ghr = gir, ghz = gir, ghn = gir;
    for (int s = 0; s < SKi; ++s) {
        const float *base = Pgi + ((size_t)s * 64 + b) * 3072;
        float4 p;
        p = *(const float4 *)(base + j);        gir.x+=p.x; gir.y+=p.y; gir.z+=p.z; gir.w+=p.w;
        p = *(const float4 *)(base + 1024 + j); giz.x+=p.x; giz.y+=p.y; giz.z+=p.z; giz.w+=p.w;
        p = *(const float4 *)(base + 2048 + j); gin.x+=p.x; gin.y+=p.y; gin.z+=p.z; gin.w+=p.w;
    }
    for (int s = 0; s < SKh; ++s) {
        const float *base = Pgh + ((size_t)s * 64 + b) * 3072;
        float4 p;
        p = *(const float4 *)(base + j);        ghr.x+=p.x; ghr.y+=p.y; ghr.z+=p.z; ghr.w+=p.w;
        p = *(const float4 *)(base + 1024 + j); ghz.x+=p.x; ghz.y+=p.y; ghz.z+=p.z; ghz.w+=p.w;
        p = *(const float4 *)(base + 2048 + j); ghn.x+=p.x; ghn.y+=p.y; ghn.z+=p.z; ghn.w+=p.w;
    }
    float4 bir = *(const float4 *)(bi + j),        bhr = *(const float4 *)(bh + j);
    float4 biz = *(const float4 *)(bi + 1024 + j), bhz = *(const float4 *)(bh + 1024 + j);
    float4 bin = *(const float4 *)(bi + 2048 + j), bhn = *(const float4 *)(bh + 2048 + j);
    float4 dv  = *(const float4 *)(det + (size_t)b * 1024 + j);

    float o[4];
    float girA[4] = {gir.x, gir.y, gir.z, gir.w}, gizA[4] = {giz.x, giz.y, giz.z, giz.w};
    float ginA[4] = {gin.x, gin.y, gin.z, gin.w};
    float ghrA[4] = {ghr.x, ghr.y, ghr.z, ghr.w}, ghzA[4] = {ghz.x, ghz.y, ghz.z, ghz.w};
    float ghnA[4] = {ghn.x, ghn.y, ghn.z, ghn.w};
    float birA[4] = {bir.x, bir.y, bir.z, bir.w}, bhrA[4] = {bhr.x, bhr.y, bhr.z, bhr.w};
    float bizA[4] = {biz.x, biz.y, biz.z, biz.w}, bhzA[4] = {bhz.x, bhz.y, bhz.z, bhz.w};
    float binA[4] = {bin.x, bin.y, bin.z, bin.w}, bhnA[4] = {bhn.x, bhn.y, bhn.z, bhn.w};
    float dvA[4]  = {dv.x, dv.y, dv.z, dv.w};
#pragma unroll
    for (int i = 0; i < 4; ++i) {
        float r  = sigm((girA[i] + birA[i]) + (ghrA[i] + bhrA[i]));
        float zt = sigm((gizA[i] + bizA[i]) + (ghzA[i] + bhzA[i]));
        float gh_n = ghnA[i] + bhnA[i];
        float n  = tanhf((ginA[i] + binA[i]) + r * gh_n);
        o[i] = (1.f - zt) * n + zt * dvA[i];
    }
    float4 dn = make_float4(o[0], o[1], o[2], o[3]);
    *(float4 *)(detn + (size_t)b * 1024 + j) = dn;
    *(float4 *)(outc + (size_t)b * ldo + j)  = dn;
}

// ---------------- head: reduce mean/std partials, sample, write out ---------
__global__ void head_fin(const float *__restrict__ P, int SK,
                         const float *__restrict__ bqm, const float *__restrict__ bqs,
                         const float *__restrict__ nq, int ldnq,
                         float *__restrict__ outr, int ldo) {
    int idx = blockIdx.x * blockDim.x + threadIdx.x;   // per float4 of [64][128]
    if (idx >= 64 * 128 / 4) return;
    int b = idx >> 5;
    int c = (idx & 31) << 2;
    const size_t sz = (size_t)SK * 64 * 128;
    float4 m = make_float4(0,0,0,0), sp = m;
    for (int s = 0; s < SK; ++s) {
        float4 p0 = *(const float4 *)(P + ((size_t)s * 64 + b) * 128 + c);
        float4 p1 = *(const float4 *)(P + sz + ((size_t)s * 64 + b) * 128 + c);
        m.x += p0.x; m.y += p0.y; m.z += p0.z; m.w += p0.w;
        sp.x += p1.x; sp.y += p1.y; sp.z += p1.z; sp.w += p1.w;
    }
    float4 bm = *(const float4 *)(bqm + c);
    float4 bs = *(const float4 *)(bqs + c);
    float4 e  = *(const float4 *)(nq + (size_t)b * ldnq + c);
    float4 o;
    o.x = (m.x + bm.x) + (softp(sp.x + bs.x) + 1e-4f) * e.x;
    o.y = (m.y + bm.y) + (softp(sp.y + bs.y) + 1e-4f) * e.y;
    o.z = (m.z + bm.z) + (softp(sp.z + bs.z) + 1e-4f) * e.z;
    o.w = (m.w + bm.w) + (softp(sp.w + bs.w) + 1e-4f) * e.w;
    *(float4 *)(outr + (size_t)b * ldo + c) = o;
}

__global__ void zero_buf(float *p, int n) {
    int i = (blockIdx.x * blockDim.x + threadIdx.x) * 4;
    if (i < n) *(float4 *)(p + i) = make_float4(0.f, 0.f, 0.f, 0.f);
}

// ---------------- host driver ------------------------------------------------
extern "C" void kernel_launch(void* const* d_in, const int* in_sizes, int n_in,
                              void* d_out, int out_size) {
    // --- input mapping: dict order (x0,np0,nq0,...) vs signature order ---
    const float *X[3], *NQ[3];
    bool dictOrder = (in_sizes[1] == 64 * 36 * 128);
    if (dictOrder) {
        X[0] = (const float *)d_in[0]; NQ[0] = (const float *)d_in[2];
        X[1] = (const float *)d_in[3]; NQ[1] = (const float *)d_in[5];
        X[2] = (const float *)d_in[6]; NQ[2] = (const float *)d_in[8];
    } else {
        for (int l = 0; l < 3; ++l) {
            X[l]  = (const float *)d_in[l];
            NQ[l] = (const float *)d_in[6 + l];
        }
    }
    const float *w1  = (const float *)d_in[9];
    const float *b1  = (const float *)d_in[10];
    const float *gwi = (const float *)d_in[11];
    const float *gwh = (const float *)d_in[12];
    const float *gbi = (const float *)d_in[13];
    const float *gbh = (const float *)d_in[14];
    // d_in[15..20] = w2,b2,wpm,bpm,wps,bps : dead code (prior head unused)
    const float *q1  = (const float *)d_in[21];
    const float *qb1 = (const float *)d_in[22];
    const float *q2  = (const float *)d_in[23];
    const float *qb2 = (const float *)d_in[24];
    const float *wqm = (const float *)d_in[25];
    const float *bqm = (const float *)d_in[26];
    const float *wqs = (const float *)d_in[27];
    const float *bqs = (const float *)d_in[28];

    float *P, *Pgh, *Pgi, *h, *hq1, *hq2, *detbase, *o1, *o2;
    cudaGetSymbolAddress((void **)&P,      g_P);
    cudaGetSymbolAddress((void **)&Pgh,    g_Pgh);
    cudaGetSymbolAddress((void **)&Pgi,    g_Pgi);
    cudaGetSymbolAddress((void **)&h,      g_h);
    cudaGetSymbolAddress((void **)&hq1,    g_hq1);
    cudaGetSymbolAddress((void **)&hq2,    g_hq2);
    cudaGetSymbolAddress((void **)&detbase,g_det);
    cudaGetSymbolAddress((void **)&o1,     g_out1);
    cudaGetSymbolAddress((void **)&o2,     g_out2);
    float *det[2] = {detbase, detbase + 64 * 1024};

    float *OUT[3] = {(float *)d_out, o1, o2};
    const int Tl[3] = {36, 6, 1};

    for (int l = 2; l >= 0; --l) {
        const int T = Tl[l];
        const float *w1l  = w1  + (size_t)l * 1280 * 1024;
        const float *b1l  = b1  + (size_t)l * 1024;
        const float *gwil = gwi + (size_t)l * 1024 * 3072;
        const float *gwhl = gwh + (size_t)l * 1024 * 3072;
        const float *gbil = gbi + (size_t)l * 3072;
        const float *gbhl = gbh + (size_t)l * 3072;
        const float *q1l  = q1  + (size_t)l * 2048 * 1024;
        const float *qb1l = qb1 + (size_t)l * 1024;
        const float *q2l  = q2  + (size_t)l * 1024 * 1024;
        const float *qb2l = qb2 + (size_t)l * 1024;
        const float *wqml = wqm + (size_t)l * 1024 * 128;
        const float *bqml = bqm + (size_t)l * 128;
        const float *wqsl = wqs + (size_t)l * 1024 * 128;
        const float *bqsl = bqs + (size_t)l * 128;

        float *out_l = OUT[l];
        const float *out_up = (l < 2) ? OUT[l + 1] : nullptr;
        const int Tup = (l < 2) ? Tl[l + 1] : 1;

        zero_buf<<<64, 256>>>(det[0], 64 * 1024);
        int cur = 0;
        for (int t = 0; t < T; ++t) {
            int nxt = cur ^ 1;
            const float *samp = (t > 0) ? out_l + (size_t)(t - 1) * OO : nullptr;
            const float *ctx  = out_up ? out_up + (size_t)(t / FF) * OO : nullptr;

            // prior dense h = elu([sample|ctx] @ w1 + b1)  (merged with gh GEMM)
            GemmDesc dh  = {samp, ctx, w1l, P,   T * OO, Tup * OO, 128, 1152, 1024, 8, 160, 8};
            GemmDesc dgh = {det[cur], nullptr, gwhl, Pgh, 1024, 0, 1024, 0, 3072, 4, 256, 24};
            gemm_part2<<<64 + 96, 128>>>(dh, dgh, 64);
            reduce_act<<<64, 256>>>(P, 8, 1024, b1l, h, 1);

            // gi = h @ gru_wi  (partials), then fused GRU
            GemmDesc dgi = {h, nullptr, gwil, Pgi, 1024, 0, 1024, 0, 3072, 8, 128, 24};
            gemm_part2<<<192, 128>>>(dgi, dgi, 192);
            gru_fuse<<<64, 256>>>(Pgi, 8, Pgh, 4, gbil, gbhl, det[cur], det[nxt],
                                  out_l + (size_t)t * OO + 128, T * OO);

            // posterior: hq1 = elu([det_new|obs] @ q1 + qb1)
            GemmDesc dq1 = {det[nxt], X[l] + (size_t)t * EE, q1l, P,
                            1024, T * EE, 1024, 1024, 1024, 16, 128, 8};
            gemm_part2<<<128, 128>>>(dq1, dq1, 128);
            reduce_act<<<64, 256>>>(P, 16, 1024, qb1l, hq1, 1);

            // hq2 = elu(hq1 @ q2 + qb2)
            GemmDesc dq2 = {hq1, nullptr, q2l, P, 1024, 0, 1024, 0, 1024, 16, 64, 8};
            gemm_part2<<<128, 128>>>(dq2, dq2, 128);
            reduce_act<<<64, 256>>>(P, 16, 1024, qb2l, hq2, 1);

            // head: mean / std partials, then sample + write out[:, t, 0:128]
            GemmDesc dm = {hq2, nullptr, wqml, P,                1024, 0, 1024, 0, 128, 8, 128, 1};
            GemmDesc ds = {hq2, nullptr, wqsl, P + 8 * 64 * 128, 1024, 0, 1024, 0, 128, 8, 128, 1};
            gemm_part2<<<16, 128>>>(dm, ds, 8);
            head_fin<<<8, 256>>>(P, 8, bqml, bqsl, NQ[l] + (size_t)t * SS, T * SS,
                                 out_l + (size_t)t * OO, T * OO);
            cur = nxt;
        }
    }
    (void)n_in; (void)out_size;
}